// round 14
// baseline (speedup 1.0000x reference)
#include <cuda_runtime.h>
#include <cstdint>

// Problem constants (fixed by dataset): B=1, N=4096, C=8, H=W=128, K=8
#define MAXN 8192
constexpr float RADIUS = 0.05f;
constexpr int H = 128, W = 128, C = 8, K = 8;
constexpr int TILE = 8;             // 8x8 pixel tiles
constexpr int TX = W / TILE;        // 16
constexpr int TY = H / TILE;        // 16
constexpr int NTILES = TX * TY;     // 256 tiles
constexpr int NBLK = NTILES / 2;    // 128 CTAs, 2 adjacent tiles each (<= 148 SMs)
constexpr int PIX2 = 2 * TILE * TILE;  // 128 pixels per CTA
constexpr int TPB = 512;
constexpr int CAPT = 256;           // per-tile candidate cap (mean ~52, max ~90)
constexpr int PIXCAP = 36;          // per-pixel hit cap (mean ~8, Poisson tail ~1e-13)

// smem layout (45056 B static + counters):
//   [    0,  8192)  s_cand  float4[2][256]   (dead after phase 2)
//   [ 8192, 26624)  s_hz    float[128][36]
//   [26624, 45056)  s_hi    int  [128][36]
//   [    0,  4096)  s_wk    float[128][8]  ── aliases s_cand in phase 3
//   [ 4096,  8192)  s_ik    int  [128][8]  ──
constexpr int RAWSZ = 45056;

__global__ void __launch_bounds__(TPB)
render_kernel(const float* __restrict__ pts,
              const float* __restrict__ feat,
              float* __restrict__ out, int n) {
    __shared__ __align__(16) unsigned char raw[RAWSZ];
    float4* s_cand = (float4*)raw;
    float*  s_hz   = (float*)(raw + 8192);
    int*    s_hi   = (int*)  (raw + 26624);
    float*  s_wk   = (float*)raw;            // alias (phase 3)
    int*    s_ik   = (int*)  (raw + 4096);   // alias (phase 3)
    __shared__ int s_cnt[2];
    __shared__ int s_pixcnt[PIX2];

    const int tile0 = blockIdx.x * 2;        // two tiles in the same row (TX even)
    const int tx0 = tile0 & (TX - 1);
    const int ty  = tile0 >> 4;
    const int tid = threadIdx.x;

    if (tid < PIX2) s_pixcnt[tid] = 0;
    if (tid < 2)    s_cnt[tid] = 0;
    __syncthreads();

    // ---- bboxes over pixel centers, expanded by splat radius + eps (NDC) ----
    const float EPS = 1e-5f;
    // union bbox of both tiles (16x8 pixels)
    const float ux0 = ((float)(tx0 * TILE)      + 0.5f) * (2.0f / W) - 1.0f - RADIUS - EPS;
    const float ux1 = ((float)(tx0 * TILE + 15) + 0.5f) * (2.0f / W) - 1.0f + RADIUS + EPS;
    const float uy0 = ((float)(ty * TILE)       + 0.5f) * (2.0f / H) - 1.0f - RADIUS - EPS;
    const float uy1 = ((float)(ty * TILE + 7)   + 0.5f) * (2.0f / H) - 1.0f + RADIUS + EPS;
    // per-tile x bounds (y is shared)
    float tbx0[2], tbx1[2];
    #pragma unroll
    for (int hf = 0; hf < 2; hf++) {
        tbx0[hf] = ((float)((tx0 + hf) * TILE)     + 0.5f) * (2.0f / W) - 1.0f - RADIUS - EPS;
        tbx1[hf] = ((float)((tx0 + hf) * TILE + 7) + 0.5f) * (2.0f / W) - 1.0f + RADIUS + EPS;
    }

    // ---- Phase 1: cull all points vs UNION bbox (division-free, coalesced
    //      scalar loads — R10-proven), classify into the 2 per-tile lists ----
    #pragma unroll
    for (int it = 0; it < MAXN / TPB; it++) {
        int i = it * TPB + tid;
        if (i < n) {
            float x = pts[3 * i + 0];
            float y = pts[3 * i + 1];
            float z = pts[3 * i + 2];
            // z>0: x/z >= ux0  <=>  x >= ux0*z  (conservative; exact test later)
            bool hit = (z > 0.0f) &&
                       (x >= ux0 * z) && (x <= ux1 * z) &&
                       (y >= uy0 * z) && (y <= uy1 * z);
            if (hit) {
                float px = x / z;          // exact IEEE, matches reference
                float py = y / z;
                float4 rec = make_float4(px, py, z, __int_as_float(i));
                #pragma unroll
                for (int t = 0; t < 2; t++) {
                    if (px >= tbx0[t] && px <= tbx1[t]) {
                        int slot = atomicAdd(&s_cnt[t], 1);
                        if (slot < CAPT) s_cand[t * CAPT + slot] = rec;
                    }
                }
            }
        }
    }
    __syncthreads();

    // ---- Phase 2: 4 lanes per pixel scan the owning tile's list ------------
    const int p  = tid >> 2;               // pixel 0..127
    const int s4 = tid & 3;                // lane 0..3
    const int t  = p >> 6;                 // tile half 0..1
    const int lp = p & 63;
    const int lx = lp & (TILE - 1);
    const int ly = lp >> 3;
    const float gx = ((float)((tx0 + t) * TILE + lx) + 0.5f) * (2.0f / W) - 1.0f;
    const float gy = ((float)(ty * TILE + ly)        + 0.5f) * (2.0f / H) - 1.0f;
    const float r2 = RADIUS * RADIUS;
    {
        const int cnt = min(s_cnt[t], CAPT);
        for (int j = s4; j < cnt; j += 4) {
            float4 cd = s_cand[t * CAPT + j];
            float dx = gx - cd.x;
            float dy = gy - cd.y;
            float d2 = dx * dx + dy * dy;
            if (d2 < r2) {                 // exact hit test (matches reference)
                int slot = atomicAdd(&s_pixcnt[p], 1);
                if (slot < PIXCAP) {
                    s_hz[p * PIXCAP + slot] = cd.z;
                    s_hi[p * PIXCAP + slot] = __float_as_int(cd.w);
                }
            }
        }
    }
    __syncthreads();   // also protects the s_cand -> s_wk/s_ik aliasing below

    // ---- Phase 3a: one thread per pixel: top-8 by z, weights -> smem -------
    if (tid < PIX2) {
        const int pp = tid;
        const int hc = min(s_pixcnt[pp], PIXCAP);
        const int tt = pp >> 6;
        const int llx = pp & (TILE - 1);
        const int lly = (pp & 63) >> 3;
        const float pgx = ((float)((tx0 + tt) * TILE + llx) + 0.5f) * (2.0f / W) - 1.0f;
        const float pgy = ((float)(ty * TILE + lly)         + 0.5f) * (2.0f / H) - 1.0f;

        float lz[K];
        int   li[K];
        #pragma unroll
        for (int k = 0; k < K; k++) { lz[k] = 3.0e38f; li[k] = 0; }
        for (int j = 0; j < hc; j++) {
            float z = s_hz[pp * PIXCAP + j];
            // distinct depths -> top-K set is order-independent (matches top_k)
            if (z < lz[K - 1]) {
                lz[K - 1] = z; li[K - 1] = s_hi[pp * PIXCAP + j];
                #pragma unroll
                for (int k = K - 1; k > 0; k--) {
                    if (lz[k] < lz[k - 1]) {
                        float t0 = lz[k]; lz[k] = lz[k - 1]; lz[k - 1] = t0;
                        int   t2 = li[k]; li[k] = li[k - 1]; li[k - 1] = t2;
                    }
                }
            }
        }

        // reload winners' x,y (8 independent pairs, one latency round);
        // px = x/z with the SAME z bits -> identical projection as phase 1
        float pxk[K], pyk[K];
        #pragma unroll
        for (int k = 0; k < K; k++) {
            int id = (lz[k] < 1.0e38f) ? li[k] : 0;
            float x = __ldg(&pts[3 * id + 0]);
            float y = __ldg(&pts[3 * id + 1]);
            pxk[k] = x / lz[k];            // invalid: x/3e38 ~ 0, weight forced 0
            pyk[k] = y / lz[k];
        }

        float T = 1.0f;
        const float inv_r2 = 1.0f / r2;
        #pragma unroll
        for (int k = 0; k < K; k++) {
            bool valid = lz[k] < 1.0e38f;
            float dx = pgx - pxk[k];
            float dy = pgy - pyk[k];
            float d2 = dx * dx + dy * dy;
            float a = fminf(fmaxf(1.0f - d2 * inv_r2, 0.0f), 1.0f);
            a = valid ? a : 0.0f;
            s_wk[pp * K + k] = a * T;
            s_ik[pp * K + k] = valid ? li[k] : 0;
            T *= (1.0f - a);
        }
    }
    __syncthreads();

    // ---- Phase 3b: 2 threads per pixel gather features (one parallel round)
    if (tid < 2 * PIX2) {
        const int pp = tid >> 1;           // pixel 0..127
        const int hf = tid & 1;            // channel half
        float4 F[K];
        float  wks[K];
        #pragma unroll
        for (int k = 0; k < K; k++) {
            wks[k] = s_wk[pp * K + k];
            int id = s_ik[pp * K + k];
            F[k] = __ldg(&((const float4*)(feat + (size_t)id * C))[hf]);
        }
        float a0 = 0.0f, a1 = 0.0f, a2 = 0.0f, a3 = 0.0f;
        #pragma unroll
        for (int k = 0; k < K; k++) {
            a0 += wks[k] * F[k].x;
            a1 += wks[k] * F[k].y;
            a2 += wks[k] * F[k].z;
            a3 += wks[k] * F[k].w;
        }
        const int tt = pp >> 6;
        const int pix_x = (tx0 + tt) * TILE + (pp & (TILE - 1));
        const int pix_y = ty * TILE + ((pp & 63) >> 3);
        float4* o = (float4*)(out + (size_t)(pix_y * W + pix_x) * C);
        o[hf] = make_float4(a0, a1, a2, a3);
    }
}

extern "C" void kernel_launch(void* const* d_in, const int* in_sizes, int n_in,
                              void* d_out, int out_size) {
    const float* pts  = (const float*)d_in[0];   // [B,N,3] f32
    const float* feat = (const float*)d_in[1];   // [B,N,C] f32
    float* out = (float*)d_out;                  // [B,H,W,C] f32
    int n = in_sizes[0] / 3;                     // B=1 -> N
    if (n > MAXN) n = MAXN;

    render_kernel<<<NBLK, TPB>>>(pts, feat, out, n);
}